// round 14
// baseline (speedup 1.0000x reference)
#include <cuda_runtime.h>
#include <cuda_bf16.h>
#include <cuda_fp16.h>
#include <cstdint>

// Problem constants
#define NN   30000
#define EE   480000
#define ET   (EE + NN)
#define INF_ 256
#define OUTF 128
#define HH   4
#define HC   (HH * OUTF)      // 512
#define NEG_SLOPE 0.2f
#define NB   ((NN + 511) / 512)   // 59 scan blocks
#define WCAP 128                  // per-warp edge-weight smem cap

// ---------------- device scratch ----------------
__device__ __half         g_h[(size_t)NN * HC];        // projected features, fp16 (30.7 MB)
__device__ float          g_as[NN * HH];
__device__ float          g_ad[NN * HH];
__device__ __half         g_x[(size_t)NN * INF_];      // x in fp16 (15.4 MB)
__device__ __half         g_Wt[HC * INF_];             // W^T fp16 [512][256]
__device__ int            g_deg[NN];
__device__ int            g_off[NN + 1];
__device__ int            g_pos[NN];
__device__ int            g_bin[ET];
__device__ int            g_bsum[64];
__device__ int            g_bpre[64];

__device__ __forceinline__ float lrelu(float f) { return f > 0.0f ? f : NEG_SLOPE * f; }

__device__ __forceinline__ uint32_t smem_u32(const void* p) {
    uint32_t a;
    asm("{ .reg .u64 t; cvta.to.shared.u64 t, %1; cvt.u32.u64 %0, t; }" : "=r"(a) : "l"(p));
    return a;
}
__device__ __forceinline__ void ldsm4(uint32_t* r, uint32_t addr) {
    asm volatile("ldmatrix.sync.aligned.m8n8.x4.shared.b16 {%0,%1,%2,%3}, [%4];"
                 : "=r"(r[0]), "=r"(r[1]), "=r"(r[2]), "=r"(r[3]) : "r"(addr));
}
__device__ __forceinline__ void mma_f16(float* c, const uint32_t* a, const uint32_t* b) {
    asm volatile(
        "mma.sync.aligned.m16n8k16.row.col.f32.f16.f16.f32 "
        "{%0,%1,%2,%3}, {%4,%5,%6,%7}, {%8,%9}, {%0,%1,%2,%3};"
        : "+f"(c[0]), "+f"(c[1]), "+f"(c[2]), "+f"(c[3])
        : "r"(a[0]), "r"(a[1]), "r"(a[2]), "r"(a[3]), "r"(b[0]), "r"(b[1]));
}
__device__ __forceinline__ void cp16(uint32_t saddr, const void* gptr) {
    asm volatile("cp.async.ca.shared.global [%0], [%1], 16;"
                 :: "r"(saddr), "l"(gptr));
}
#define CP_COMMIT()  asm volatile("cp.async.commit_group;" ::: "memory")
#define CP_WAIT(n)   asm volatile("cp.async.wait_group %0;" :: "n"(n) : "memory")

// ---------------- 0) prep: x -> fp16; W^T fp16; zero attn accum ----
__global__ void prep_kernel(const float* __restrict__ x, const float* __restrict__ W) {
    const int idx = blockIdx.x * blockDim.x + threadIdx.x;
    if (idx < NN * INF_) {
        g_x[idx] = __float2half_rn(x[idx]);
    }
    if (idx < HC * INF_) {
        const int n = idx >> 8;
        const int k = idx & 255;
        g_Wt[idx] = __float2half_rn(W[(size_t)k * HC + n]);
    }
    if (idx < NN * HH) { g_as[idx] = 0.0f; g_ad[idx] = 0.0f; }
}

// head of the CSR side-chain: zero the degree histogram
__global__ void init_deg_kernel() {
    const int idx = blockIdx.x * blockDim.x + threadIdx.x;
    if (idx < NN) g_deg[idx] = 0;
}

__global__ void hist_kernel(const int* __restrict__ dst) {
    const int e = blockIdx.x * blockDim.x + threadIdx.x;
    if (e >= ET) return;
    const int d = (e < EE) ? dst[e] : (e - EE);
    atomicAdd(&g_deg[d], 1);
}

// ---------------- 1) GEMM via mma.sync fp16 (single term), cp.async 2-stage -------
// Block 128(M) x 128(N)=one head, 8 warps (4x2), warp tile 32x64.
__global__ void __launch_bounds__(256) gemm_mma_kernel(const float* __restrict__ att_src,
                                                       const float* __restrict__ att_dst) {
    __shared__ __align__(16) __half As[2][128][40];
    __shared__ __align__(16) __half Bs[2][128][40];

    const int tid    = threadIdx.x;
    const int lane   = tid & 31;
    const int wid    = tid >> 5;
    const int warp_m = wid & 3;
    const int warp_n = wid >> 2;
    const int bm     = blockIdx.x * 128;
    const int n0     = blockIdx.y * 128;
    const int head   = blockIdx.y;

    float acc[2][8][4];
#pragma unroll
    for (int i = 0; i < 2; i++)
#pragma unroll
        for (int j = 0; j < 8; j++)
#pragma unroll
            for (int k = 0; k < 4; k++) acc[i][j][k] = 0.0f;

    const uint32_t as_base = smem_u32(&As[0][0][0]);
    const uint32_t bs_base = smem_u32(&Bs[0][0][0]);
    const int a_row = warp_m * 32 + (lane & 15);
    const int a_col = (lane >> 4) * 8;
    const int b_row = warp_n * 64 + (lane & 7) + (lane >> 4) * 8;
    const int b_col = ((lane >> 3) & 1) * 8;

    const int NITER = 8;   // 8 K-chunks of 32

    auto prefetch = [&](int stage, int it) {
        const int k0 = it << 5;
#pragma unroll
        for (int i = 0; i < 2; i++) {
            const int idx = tid + i * 256;
            const int row = idx >> 2;
            const int seg = (idx & 3) * 8;
            const int gr  = bm + row;
            const int grc = (gr < NN) ? gr : 0;   // clamp; results discarded later
            cp16(as_base + (((stage * 128 + row) * 40) + seg) * 2,
                 g_x + (size_t)grc * INF_ + k0 + seg);
            cp16(bs_base + (((stage * 128 + row) * 40) + seg) * 2,
                 g_Wt + (size_t)(n0 + row) * INF_ + k0 + seg);
        }
        CP_COMMIT();
    };

    prefetch(0, 0);
#pragma unroll 1
    for (int it = 0; it < NITER; it++) {
        const int stage = it & 1;
        if (it + 1 < NITER) {
            prefetch(stage ^ 1, it + 1);
            CP_WAIT(1);
        } else {
            CP_WAIT(0);
        }
        __syncthreads();
#pragma unroll
        for (int ks = 0; ks < 2; ks++) {
            uint32_t af[2][4];
#pragma unroll
            for (int mt = 0; mt < 2; mt++) {
                const uint32_t addr = as_base +
                    ((stage * 128 + a_row + mt * 16) * 40 + ks * 16 + a_col) * 2;
                ldsm4(af[mt], addr);
            }
#pragma unroll
            for (int p = 0; p < 4; p++) {
                uint32_t bf[4];
                const uint32_t addr = bs_base +
                    ((stage * 128 + b_row + p * 16) * 40 + ks * 16 + b_col) * 2;
                ldsm4(bf, addr);
#pragma unroll
                for (int mt = 0; mt < 2; mt++) {
                    mma_f16(acc[mt][2 * p],     af[mt], bf);
                    mma_f16(acc[mt][2 * p + 1], af[mt], bf + 2);
                }
            }
        }
        __syncthreads();
    }

    // ---- epilogue: store g_h (fp16), fused attention dot partials ----
    const int r0 = lane >> 2;
    const int cq = (lane & 3) * 2;
    float da[2][2] = {{0.f, 0.f}, {0.f, 0.f}};
    float db[2][2] = {{0.f, 0.f}, {0.f, 0.f}};

#pragma unroll
    for (int mt = 0; mt < 2; mt++) {
        const int gm0 = bm + warp_m * 32 + mt * 16 + r0;
        const int gm1 = gm0 + 8;
#pragma unroll
        for (int nt = 0; nt < 8; nt++) {
            const int cih = warp_n * 64 + nt * 8 + cq;
            const int gc  = n0 + cih;
            const float s0 = att_src[head * OUTF + cih];
            const float s1 = att_src[head * OUTF + cih + 1];
            const float d0 = att_dst[head * OUTF + cih];
            const float d1 = att_dst[head * OUTF + cih + 1];
            const float c0 = acc[mt][nt][0], c1 = acc[mt][nt][1];
            const float c2 = acc[mt][nt][2], c3 = acc[mt][nt][3];
            da[mt][0] += c0 * s0 + c1 * s1;
            db[mt][0] += c0 * d0 + c1 * d1;
            da[mt][1] += c2 * s0 + c3 * s1;
            db[mt][1] += c2 * d0 + c3 * d1;
            if (gm0 < NN)
                *(__half2*)&g_h[(size_t)gm0 * HC + gc] = __floats2half2_rn(c0, c1);
            if (gm1 < NN)
                *(__half2*)&g_h[(size_t)gm1 * HC + gc] = __floats2half2_rn(c2, c3);
        }
    }
#pragma unroll
    for (int mt = 0; mt < 2; mt++)
#pragma unroll
        for (int h = 0; h < 2; h++) {
            da[mt][h] += __shfl_xor_sync(0xFFFFFFFFu, da[mt][h], 1);
            da[mt][h] += __shfl_xor_sync(0xFFFFFFFFu, da[mt][h], 2);
            db[mt][h] += __shfl_xor_sync(0xFFFFFFFFu, db[mt][h], 1);
            db[mt][h] += __shfl_xor_sync(0xFFFFFFFFu, db[mt][h], 2);
        }
    if ((lane & 3) == 0) {
#pragma unroll
        for (int mt = 0; mt < 2; mt++)
#pragma unroll
            for (int h = 0; h < 2; h++) {
                const int gm = bm + warp_m * 32 + mt * 16 + r0 + h * 8;
                if (gm < NN) {
                    atomicAdd(&g_as[gm * HH + head], da[mt][h]);
                    atomicAdd(&g_ad[gm * HH + head], db[mt][h]);
                }
            }
    }
}

// ---------------- 2) CSR build: hierarchical scan + fill ----------------
__global__ void __launch_bounds__(512) scanA_kernel() {
    __shared__ int sm[512];
    const int t = threadIdx.x;
    const int j = blockIdx.x * 512 + t;
    const int v = (j < NN) ? g_deg[j] : 0;
    sm[t] = v;
    __syncthreads();
#pragma unroll
    for (int s = 1; s < 512; s <<= 1) {
        const int u = (t >= s) ? sm[t - s] : 0;
        __syncthreads();
        sm[t] += u;
        __syncthreads();
    }
    if (j < NN) g_off[j] = sm[t] - v;
    if (t == 511) g_bsum[blockIdx.x] = sm[511];
}

__global__ void __launch_bounds__(64) scanB_kernel() {
    __shared__ int sm[64];
    const int t = threadIdx.x;
    const int v = (t < NB) ? g_bsum[t] : 0;
    sm[t] = v;
    __syncthreads();
#pragma unroll
    for (int s = 1; s < 64; s <<= 1) {
        const int u = (t >= s) ? sm[t - s] : 0;
        __syncthreads();
        sm[t] += u;
        __syncthreads();
    }
    if (t < NB) g_bpre[t] = sm[t] - v;
}

__global__ void __launch_bounds__(512) scanC_kernel() {
    const int j = blockIdx.x * 512 + threadIdx.x;
    if (j < NN) {
        const int o = g_off[j] + g_bpre[blockIdx.x];
        g_off[j] = o;
        g_pos[j] = o;
    }
    if (j == 0) g_off[NN] = ET;
}

__global__ void fill_kernel(const int* __restrict__ src, const int* __restrict__ dst) {
    const int e = blockIdx.x * blockDim.x + threadIdx.x;
    if (e >= ET) return;
    int s, d;
    if (e < EE) { s = src[e]; d = dst[e]; } else { s = d = e - EE; }
    const int p = atomicAdd(&g_pos[d], 1);
    g_bin[p] = s;
}

// ---------------- 3) gather aggregation: 2 warps per node (channel split) ----------
// Warp pair (node, half): each warp owns 64 of the 128 output channels
// (lane holds 2 channels per head). Passes 1-2 (softmax) run redundantly per
// warp (trivial cost); pass 2 caches exp values in smem, normalized in place;
// pass 3 gathers 512 B/edge per warp. Disjoint outputs -> no cross-warp combine.
__global__ void __launch_bounds__(256) aggregate_kernel(float* __restrict__ out,
                                                        const float* __restrict__ bias) {
    __shared__ __align__(16) float4 wbuf[8][WCAP];   // 16 KB
    const int wib  = threadIdx.x >> 5;               // warp in block
    const int gw   = (blockIdx.x * blockDim.x + threadIdx.x) >> 5;
    const int lane = threadIdx.x & 31;
    if (gw >= 2 * NN) return;
    const int d    = gw >> 1;
    const int half = gw & 1;
    const int off = g_off[d];
    const int end = g_off[d + 1];
    const float4 ad4 = *(const float4*)&g_ad[d * HH];

    // pass 1: per-head max
    float4 m = make_float4(-1e30f, -1e30f, -1e30f, -1e30f);
    for (int i = off + lane; i < end; i += 32) {
        const int s = g_bin[i];
        const float4 as4 = *(const float4*)&g_as[s * HH];
        m.x = fmaxf(m.x, lrelu(as4.x + ad4.x));
        m.y = fmaxf(m.y, lrelu(as4.y + ad4.y));
        m.z = fmaxf(m.z, lrelu(as4.z + ad4.z));
        m.w = fmaxf(m.w, lrelu(as4.w + ad4.w));
    }
#pragma unroll
    for (int o = 16; o; o >>= 1) {
        m.x = fmaxf(m.x, __shfl_xor_sync(0xFFFFFFFFu, m.x, o));
        m.y = fmaxf(m.y, __shfl_xor_sync(0xFFFFFFFFu, m.y, o));
        m.z = fmaxf(m.z, __shfl_xor_sync(0xFFFFFFFFu, m.z, o));
        m.w = fmaxf(m.w, __shfl_xor_sync(0xFFFFFFFFu, m.w, o));
    }
    // pass 2: denominators; cache exp values in smem
    float4 den = make_float4(0.f, 0.f, 0.f, 0.f);
    for (int i = off + lane; i < end; i += 32) {
        const int s = g_bin[i];
        const float4 as4 = *(const float4*)&g_as[s * HH];
        float4 ex;
        ex.x = __expf(lrelu(as4.x + ad4.x) - m.x);
        ex.y = __expf(lrelu(as4.y + ad4.y) - m.y);
        ex.z = __expf(lrelu(as4.z + ad4.z) - m.z);
        ex.w = __expf(lrelu(as4.w + ad4.w) - m.w);
        den.x += ex.x; den.y += ex.y; den.z += ex.z; den.w += ex.w;
        const int idx = i - off;
        if (idx < WCAP) wbuf[wib][idx] = ex;
    }
#pragma unroll
    for (int o = 16; o; o >>= 1) {
        den.x += __shfl_xor_sync(0xFFFFFFFFu, den.x, o);
        den.y += __shfl_xor_sync(0xFFFFFFFFu, den.y, o);
        den.z += __shfl_xor_sync(0xFFFFFFFFu, den.z, o);
        den.w += __shfl_xor_sync(0xFFFFFFFFu, den.w, o);
    }
    const float4 inv = make_float4(0.25f / den.x, 0.25f / den.y, 0.25f / den.z, 0.25f / den.w);
    __syncwarp();
    // normalize cached weights in place
    {
        const int cnt = end - off;
        const int lim = cnt < WCAP ? cnt : WCAP;
        for (int idx = lane; idx < lim; idx += 32) {
            float4 w4 = wbuf[wib][idx];
            w4.x *= inv.x; w4.y *= inv.y; w4.z *= inv.z; w4.w *= inv.w;
            wbuf[wib][idx] = w4;
        }
    }
    __syncwarp();

    // pass 3: weighted feature gather; this warp owns channels [half*64, half*64+64)
    float2 acc = make_float2(0.f, 0.f);
    const int cb = half * 64 + lane * 2;   // 2 channels per head per lane

    auto body = [&](int i) {
        const int idx = i - off;
        float4 w4;
        if (idx < WCAP) {
            w4 = wbuf[wib][idx];
        } else {   // astronomically rare (deg > 128): recompute inline
            const float4 as4 = *(const float4*)&g_as[g_bin[i] * HH];
            w4.x = __expf(lrelu(as4.x + ad4.x) - m.x) * inv.x;
            w4.y = __expf(lrelu(as4.y + ad4.y) - m.y) * inv.y;
            w4.z = __expf(lrelu(as4.z + ad4.z) - m.z) * inv.z;
            w4.w = __expf(lrelu(as4.w + ad4.w) - m.w) * inv.w;
        }
        const __half* hs = &g_h[(size_t)g_bin[i] * HC];
        const float2 f0 = __half22float2(*(const __half2*)(hs + 0 * OUTF + cb));
        const float2 f1 = __half22float2(*(const __half2*)(hs + 1 * OUTF + cb));
        const float2 f2 = __half22float2(*(const __half2*)(hs + 2 * OUTF + cb));
        const float2 f3 = __half22float2(*(const __half2*)(hs + 3 * OUTF + cb));
        acc.x += w4.x * f0.x + w4.y * f1.x + w4.z * f2.x + w4.w * f3.x;
        acc.y += w4.x * f0.y + w4.y * f1.y + w4.z * f2.y + w4.w * f3.y;
    };
    int i = off;
    for (; i + 1 < end; i += 2) { body(i); body(i + 1); }
    if (i < end) body(i);

    const float2 b2 = *(const float2*)&bias[cb];
    float2 r;
    r.x = tanhf(acc.x + b2.x);
    r.y = tanhf(acc.y + b2.y);
    *(float2*)&out[(size_t)d * OUTF + cb] = r;
}

// ---------------- launch: two-stream fork/join (graph-capturable) ----------------
struct SideStream {
    cudaStream_t s;
    cudaEvent_t  fork, join;
    SideStream() {
        cudaStreamCreateWithFlags(&s, cudaStreamNonBlocking);
        cudaEventCreateWithFlags(&fork, cudaEventDisableTiming);
        cudaEventCreateWithFlags(&join, cudaEventDisableTiming);
    }
};

extern "C" void kernel_launch(void* const* d_in, const int* in_sizes, int n_in,
                              void* d_out, int out_size) {
    const float* x       = (const float*)d_in[0];
    const int*   eidx    = (const int*)  d_in[1];
    const float* W       = (const float*)d_in[2];
    const float* att_src = (const float*)d_in[3];
    const float* att_dst = (const float*)d_in[4];
    const float* bias    = (const float*)d_in[5];
    float*       out     = (float*)d_out;

    const int* src = eidx;
    const int* dst = eidx + EE;

    static SideStream ss;   // created once, host-side only (no device allocs)

    // fork: side stream builds the CSR while main stream runs prep+GEMM
    cudaEventRecord(ss.fork, 0);
    cudaStreamWaitEvent(ss.s, ss.fork, 0);

    // side chain (independent of prep/gemm):
    init_deg_kernel<<<(NN + 255) / 256, 256, 0, ss.s>>>();
    hist_kernel<<<(ET + 255) / 256, 256, 0, ss.s>>>(dst);
    scanA_kernel<<<NB, 512, 0, ss.s>>>();
    scanB_kernel<<<1, 64, 0, ss.s>>>();
    scanC_kernel<<<NB, 512, 0, ss.s>>>();
    fill_kernel<<<(ET + 255) / 256, 256, 0, ss.s>>>(src, dst);
    cudaEventRecord(ss.join, ss.s);

    // main chain:
    prep_kernel<<<(NN * INF_ + 255) / 256, 256>>>(x, W);
    {
        dim3 grid((NN + 127) / 128, HC / 128);   // (235, 4)
        gemm_mma_kernel<<<grid, 256>>>(att_src, att_dst);
    }

    // join, then aggregate needs both chains
    cudaStreamWaitEvent(0, ss.join, 0);
    aggregate_kernel<<<(2 * NN + 7) / 8, 256>>>(out, bias);   // 2 warps per node
}

// round 15
// speedup vs baseline: 1.2120x; 1.2120x over previous
#include <cuda_runtime.h>
#include <cuda_bf16.h>
#include <cuda_fp16.h>
#include <cstdint>

// Problem constants
#define NN   30000
#define EE   480000
#define ET   (EE + NN)
#define INF_ 256
#define OUTF 128
#define HH   4
#define HC   (HH * OUTF)      // 512
#define NEG_SLOPE 0.2f
#define NB   ((NN + 511) / 512)   // 59 scan blocks
#define WCAP 128                  // per-warp edge-weight smem cap

// ---------------- device scratch ----------------
__device__ __half         g_h[(size_t)NN * HC];        // projected features, fp16 (30.7 MB)
__device__ float          g_as[NN * HH];
__device__ float          g_ad[NN * HH];
__device__ __half         g_x[(size_t)NN * INF_];      // x in fp16 (15.4 MB)
__device__ __half         g_Wt[HC * INF_];             // W^T fp16 [512][256]
__device__ int            g_deg[NN];
__device__ int            g_off[NN + 1];
__device__ int            g_pos[NN];
__device__ int            g_bin[ET];
__device__ int            g_bsum[64];
__device__ int            g_bpre[64];

__device__ __forceinline__ float lrelu(float f) { return f > 0.0f ? f : NEG_SLOPE * f; }

__device__ __forceinline__ uint32_t smem_u32(const void* p) {
    uint32_t a;
    asm("{ .reg .u64 t; cvta.to.shared.u64 t, %1; cvt.u32.u64 %0, t; }" : "=r"(a) : "l"(p));
    return a;
}
__device__ __forceinline__ void ldsm4(uint32_t* r, uint32_t addr) {
    asm volatile("ldmatrix.sync.aligned.m8n8.x4.shared.b16 {%0,%1,%2,%3}, [%4];"
                 : "=r"(r[0]), "=r"(r[1]), "=r"(r[2]), "=r"(r[3]) : "r"(addr));
}
__device__ __forceinline__ void mma_f16(float* c, const uint32_t* a, const uint32_t* b) {
    asm volatile(
        "mma.sync.aligned.m16n8k16.row.col.f32.f16.f16.f32 "
        "{%0,%1,%2,%3}, {%4,%5,%6,%7}, {%8,%9}, {%0,%1,%2,%3};"
        : "+f"(c[0]), "+f"(c[1]), "+f"(c[2]), "+f"(c[3])
        : "r"(a[0]), "r"(a[1]), "r"(a[2]), "r"(a[3]), "r"(b[0]), "r"(b[1]));
}
__device__ __forceinline__ void cp16(uint32_t saddr, const void* gptr) {
    asm volatile("cp.async.ca.shared.global [%0], [%1], 16;"
                 :: "r"(saddr), "l"(gptr));
}
#define CP_COMMIT()  asm volatile("cp.async.commit_group;" ::: "memory")
#define CP_WAIT(n)   asm volatile("cp.async.wait_group %0;" :: "n"(n) : "memory")

// ---------------- 0) prep: x -> fp16; W^T fp16; zero attn accum ----
__global__ void prep_kernel(const float* __restrict__ x, const float* __restrict__ W) {
    const int idx = blockIdx.x * blockDim.x + threadIdx.x;
    if (idx < NN * INF_) {
        g_x[idx] = __float2half_rn(x[idx]);
    }
    if (idx < HC * INF_) {
        const int n = idx >> 8;
        const int k = idx & 255;
        g_Wt[idx] = __float2half_rn(W[(size_t)k * HC + n]);
    }
    if (idx < NN * HH) { g_as[idx] = 0.0f; g_ad[idx] = 0.0f; }
}

// head of the CSR side-chain: zero the degree histogram
__global__ void init_deg_kernel() {
    const int idx = blockIdx.x * blockDim.x + threadIdx.x;
    if (idx < NN) g_deg[idx] = 0;
}

__global__ void hist_kernel(const int* __restrict__ dst) {
    const int e = blockIdx.x * blockDim.x + threadIdx.x;
    if (e >= ET) return;
    const int d = (e < EE) ? dst[e] : (e - EE);
    atomicAdd(&g_deg[d], 1);
}

// ---------------- 1) GEMM via mma.sync fp16 (single term), cp.async 2-stage -------
// Block 128(M) x 128(N)=one head, 8 warps (4x2), warp tile 32x64.
__global__ void __launch_bounds__(256) gemm_mma_kernel(const float* __restrict__ att_src,
                                                       const float* __restrict__ att_dst) {
    __shared__ __align__(16) __half As[2][128][40];
    __shared__ __align__(16) __half Bs[2][128][40];

    const int tid    = threadIdx.x;
    const int lane   = tid & 31;
    const int wid    = tid >> 5;
    const int warp_m = wid & 3;
    const int warp_n = wid >> 2;
    const int bm     = blockIdx.x * 128;
    const int n0     = blockIdx.y * 128;
    const int head   = blockIdx.y;

    float acc[2][8][4];
#pragma unroll
    for (int i = 0; i < 2; i++)
#pragma unroll
        for (int j = 0; j < 8; j++)
#pragma unroll
            for (int k = 0; k < 4; k++) acc[i][j][k] = 0.0f;

    const uint32_t as_base = smem_u32(&As[0][0][0]);
    const uint32_t bs_base = smem_u32(&Bs[0][0][0]);
    const int a_row = warp_m * 32 + (lane & 15);
    const int a_col = (lane >> 4) * 8;
    const int b_row = warp_n * 64 + (lane & 7) + (lane >> 4) * 8;
    const int b_col = ((lane >> 3) & 1) * 8;

    const int NITER = 8;   // 8 K-chunks of 32

    auto prefetch = [&](int stage, int it) {
        const int k0 = it << 5;
#pragma unroll
        for (int i = 0; i < 2; i++) {
            const int idx = tid + i * 256;
            const int row = idx >> 2;
            const int seg = (idx & 3) * 8;
            const int gr  = bm + row;
            const int grc = (gr < NN) ? gr : 0;   // clamp; results discarded later
            cp16(as_base + (((stage * 128 + row) * 40) + seg) * 2,
                 g_x + (size_t)grc * INF_ + k0 + seg);
            cp16(bs_base + (((stage * 128 + row) * 40) + seg) * 2,
                 g_Wt + (size_t)(n0 + row) * INF_ + k0 + seg);
        }
        CP_COMMIT();
    };

    prefetch(0, 0);
#pragma unroll 1
    for (int it = 0; it < NITER; it++) {
        const int stage = it & 1;
        if (it + 1 < NITER) {
            prefetch(stage ^ 1, it + 1);
            CP_WAIT(1);
        } else {
            CP_WAIT(0);
        }
        __syncthreads();
#pragma unroll
        for (int ks = 0; ks < 2; ks++) {
            uint32_t af[2][4];
#pragma unroll
            for (int mt = 0; mt < 2; mt++) {
                const uint32_t addr = as_base +
                    ((stage * 128 + a_row + mt * 16) * 40 + ks * 16 + a_col) * 2;
                ldsm4(af[mt], addr);
            }
#pragma unroll
            for (int p = 0; p < 4; p++) {
                uint32_t bf[4];
                const uint32_t addr = bs_base +
                    ((stage * 128 + b_row + p * 16) * 40 + ks * 16 + b_col) * 2;
                ldsm4(bf, addr);
#pragma unroll
                for (int mt = 0; mt < 2; mt++) {
                    mma_f16(acc[mt][2 * p],     af[mt], bf);
                    mma_f16(acc[mt][2 * p + 1], af[mt], bf + 2);
                }
            }
        }
        __syncthreads();
    }

    // ---- epilogue: store g_h (fp16), fused attention dot partials ----
    const int r0 = lane >> 2;
    const int cq = (lane & 3) * 2;
    float da[2][2] = {{0.f, 0.f}, {0.f, 0.f}};
    float db[2][2] = {{0.f, 0.f}, {0.f, 0.f}};

#pragma unroll
    for (int mt = 0; mt < 2; mt++) {
        const int gm0 = bm + warp_m * 32 + mt * 16 + r0;
        const int gm1 = gm0 + 8;
#pragma unroll
        for (int nt = 0; nt < 8; nt++) {
            const int cih = warp_n * 64 + nt * 8 + cq;
            const int gc  = n0 + cih;
            const float s0 = att_src[head * OUTF + cih];
            const float s1 = att_src[head * OUTF + cih + 1];
            const float d0 = att_dst[head * OUTF + cih];
            const float d1 = att_dst[head * OUTF + cih + 1];
            const float c0 = acc[mt][nt][0], c1 = acc[mt][nt][1];
            const float c2 = acc[mt][nt][2], c3 = acc[mt][nt][3];
            da[mt][0] += c0 * s0 + c1 * s1;
            db[mt][0] += c0 * d0 + c1 * d1;
            da[mt][1] += c2 * s0 + c3 * s1;
            db[mt][1] += c2 * d0 + c3 * d1;
            if (gm0 < NN)
                *(__half2*)&g_h[(size_t)gm0 * HC + gc] = __floats2half2_rn(c0, c1);
            if (gm1 < NN)
                *(__half2*)&g_h[(size_t)gm1 * HC + gc] = __floats2half2_rn(c2, c3);
        }
    }
#pragma unroll
    for (int mt = 0; mt < 2; mt++)
#pragma unroll
        for (int h = 0; h < 2; h++) {
            da[mt][h] += __shfl_xor_sync(0xFFFFFFFFu, da[mt][h], 1);
            da[mt][h] += __shfl_xor_sync(0xFFFFFFFFu, da[mt][h], 2);
            db[mt][h] += __shfl_xor_sync(0xFFFFFFFFu, db[mt][h], 1);
            db[mt][h] += __shfl_xor_sync(0xFFFFFFFFu, db[mt][h], 2);
        }
    if ((lane & 3) == 0) {
#pragma unroll
        for (int mt = 0; mt < 2; mt++)
#pragma unroll
            for (int h = 0; h < 2; h++) {
                const int gm = bm + warp_m * 32 + mt * 16 + r0 + h * 8;
                if (gm < NN) {
                    atomicAdd(&g_as[gm * HH + head], da[mt][h]);
                    atomicAdd(&g_ad[gm * HH + head], db[mt][h]);
                }
            }
    }
}

// ---------------- 2) CSR build: hierarchical scan + fill ----------------
__global__ void __launch_bounds__(512) scanA_kernel() {
    __shared__ int sm[512];
    const int t = threadIdx.x;
    const int j = blockIdx.x * 512 + t;
    const int v = (j < NN) ? g_deg[j] : 0;
    sm[t] = v;
    __syncthreads();
#pragma unroll
    for (int s = 1; s < 512; s <<= 1) {
        const int u = (t >= s) ? sm[t - s] : 0;
        __syncthreads();
        sm[t] += u;
        __syncthreads();
    }
    if (j < NN) g_off[j] = sm[t] - v;
    if (t == 511) g_bsum[blockIdx.x] = sm[511];
}

__global__ void __launch_bounds__(64) scanB_kernel() {
    __shared__ int sm[64];
    const int t = threadIdx.x;
    const int v = (t < NB) ? g_bsum[t] : 0;
    sm[t] = v;
    __syncthreads();
#pragma unroll
    for (int s = 1; s < 64; s <<= 1) {
        const int u = (t >= s) ? sm[t - s] : 0;
        __syncthreads();
        sm[t] += u;
        __syncthreads();
    }
    if (t < NB) g_bpre[t] = sm[t] - v;
}

__global__ void __launch_bounds__(512) scanC_kernel() {
    const int j = blockIdx.x * 512 + threadIdx.x;
    if (j < NN) {
        const int o = g_off[j] + g_bpre[blockIdx.x];
        g_off[j] = o;
        g_pos[j] = o;
    }
    if (j == 0) g_off[NN] = ET;
}

__global__ void fill_kernel(const int* __restrict__ src, const int* __restrict__ dst) {
    const int e = blockIdx.x * blockDim.x + threadIdx.x;
    if (e >= ET) return;
    int s, d;
    if (e < EE) { s = src[e]; d = dst[e]; } else { s = d = e - EE; }
    const int p = atomicAdd(&g_pos[d], 1);
    g_bin[p] = s;
}

// ---------------- 3) gather aggregation: smem-cached weights + weighted sum + tanh ----
// One warp per dst node. Pass 2 caches exp(alpha-m) per edge in smem; after the
// denominator reduce the buffer is normalized in place, so pass 3 just LDS's the
// final weight (no redundant per-lane exp recompute).
__global__ void __launch_bounds__(256) aggregate_kernel(float* __restrict__ out,
                                                        const float* __restrict__ bias) {
    __shared__ __align__(16) float4 wbuf[8][WCAP];   // 16 KB
    const int wib  = threadIdx.x >> 5;               // warp in block
    const int gw   = (blockIdx.x * blockDim.x + threadIdx.x) >> 5;
    const int lane = threadIdx.x & 31;
    if (gw >= NN) return;
    const int d   = gw;
    const int off = g_off[d];
    const int end = g_off[d + 1];
    const float4 ad4 = *(const float4*)&g_ad[d * HH];

    // pass 1: per-head max
    float4 m = make_float4(-1e30f, -1e30f, -1e30f, -1e30f);
    for (int i = off + lane; i < end; i += 32) {
        const int s = g_bin[i];
        const float4 as4 = *(const float4*)&g_as[s * HH];
        m.x = fmaxf(m.x, lrelu(as4.x + ad4.x));
        m.y = fmaxf(m.y, lrelu(as4.y + ad4.y));
        m.z = fmaxf(m.z, lrelu(as4.z + ad4.z));
        m.w = fmaxf(m.w, lrelu(as4.w + ad4.w));
    }
#pragma unroll
    for (int o = 16; o; o >>= 1) {
        m.x = fmaxf(m.x, __shfl_xor_sync(0xFFFFFFFFu, m.x, o));
        m.y = fmaxf(m.y, __shfl_xor_sync(0xFFFFFFFFu, m.y, o));
        m.z = fmaxf(m.z, __shfl_xor_sync(0xFFFFFFFFu, m.z, o));
        m.w = fmaxf(m.w, __shfl_xor_sync(0xFFFFFFFFu, m.w, o));
    }
    // pass 2: denominators; cache exp values in smem
    float4 den = make_float4(0.f, 0.f, 0.f, 0.f);
    for (int i = off + lane; i < end; i += 32) {
        const int s = g_bin[i];
        const float4 as4 = *(const float4*)&g_as[s * HH];
        float4 ex;
        ex.x = __expf(lrelu(as4.x + ad4.x) - m.x);
        ex.y = __expf(lrelu(as4.y + ad4.y) - m.y);
        ex.z = __expf(lrelu(as4.z + ad4.z) - m.z);
        ex.w = __expf(lrelu(as4.w + ad4.w) - m.w);
        den.x += ex.x; den.y += ex.y; den.z += ex.z; den.w += ex.w;
        const int idx = i - off;
        if (idx < WCAP) wbuf[wib][idx] = ex;
    }
#pragma unroll
    for (int o = 16; o; o >>= 1) {
        den.x += __shfl_xor_sync(0xFFFFFFFFu, den.x, o);
        den.y += __shfl_xor_sync(0xFFFFFFFFu, den.y, o);
        den.z += __shfl_xor_sync(0xFFFFFFFFu, den.z, o);
        den.w += __shfl_xor_sync(0xFFFFFFFFu, den.w, o);
    }
    const float4 inv = make_float4(0.25f / den.x, 0.25f / den.y, 0.25f / den.z, 0.25f / den.w);
    __syncwarp();
    // normalize cached weights in place
    {
        const int cnt = end - off;
        const int lim = cnt < WCAP ? cnt : WCAP;
        for (int idx = lane; idx < lim; idx += 32) {
            float4 w4 = wbuf[wib][idx];
            w4.x *= inv.x; w4.y *= inv.y; w4.z *= inv.z; w4.w *= inv.w;
            wbuf[wib][idx] = w4;
        }
    }
    __syncwarp();

    // pass 3: weighted feature gather (fp16 features; lane owns 4 channels per head)
    float4 acc = make_float4(0.f, 0.f, 0.f, 0.f);
    const int cb = lane * 4;

    auto body = [&](int i) {
        const int idx = i - off;
        float4 w4;
        if (idx < WCAP) {
            w4 = wbuf[wib][idx];
        } else {   // astronomically rare (deg > 128): recompute inline
            const float4 as4 = *(const float4*)&g_as[g_bin[i] * HH];
            w4.x = __expf(lrelu(as4.x + ad4.x) - m.x) * inv.x;
            w4.y = __expf(lrelu(as4.y + ad4.y) - m.y) * inv.y;
            w4.z = __expf(lrelu(as4.z + ad4.z) - m.z) * inv.z;
            w4.w = __expf(lrelu(as4.w + ad4.w) - m.w) * inv.w;
        }
        const __half* hs = &g_h[(size_t)g_bin[i] * HC];
        const uint2 u0 = *(const uint2*)(hs + 0 * OUTF + cb);
        const uint2 u1 = *(const uint2*)(hs + 1 * OUTF + cb);
        const uint2 u2 = *(const uint2*)(hs + 2 * OUTF + cb);
        const uint2 u3 = *(const uint2*)(hs + 3 * OUTF + cb);
        const float2 a0 = __half22float2(*(const __half2*)&u0.x);
        const float2 b0 = __half22float2(*(const __half2*)&u0.y);
        const float2 a1 = __half22float2(*(const __half2*)&u1.x);
        const float2 b1 = __half22float2(*(const __half2*)&u1.y);
        const float2 a2 = __half22float2(*(const __half2*)&u2.x);
        const float2 b2 = __half22float2(*(const __half2*)&u2.y);
        const float2 a3 = __half22float2(*(const __half2*)&u3.x);
        const float2 b3 = __half22float2(*(const __half2*)&u3.y);
        acc.x += w4.x * a0.x + w4.y * a1.x + w4.z * a2.x + w4.w * a3.x;
        acc.y += w4.x * a0.y + w4.y * a1.y + w4.z * a2.y + w4.w * a3.y;
        acc.z += w4.x * b0.x + w4.y * b1.x + w4.z * b2.x + w4.w * b3.x;
        acc.w += w4.x * b0.y + w4.y * b1.y + w4.z * b2.y + w4.w * b3.y;
    };
    int i = off;
    for (; i + 1 < end; i += 2) { body(i); body(i + 1); }
    if (i < end) body(i);

    const float4 b4 = *(const float4*)&bias[cb];
    float4 r;
    r.x = tanhf(acc.x + b4.x);
    r.y = tanhf(acc.y + b4.y);
    r.z = tanhf(acc.z + b4.z);
    r.w = tanhf(acc.w + b4.w);
    *(float4*)&out[(size_t)d * OUTF + cb] = r;
}

// ---------------- launch: two-stream fork/join (graph-capturable) ----------------
struct SideStream {
    cudaStream_t s;
    cudaEvent_t  fork, join;
    SideStream() {
        cudaStreamCreateWithFlags(&s, cudaStreamNonBlocking);
        cudaEventCreateWithFlags(&fork, cudaEventDisableTiming);
        cudaEventCreateWithFlags(&join, cudaEventDisableTiming);
    }
};

extern "C" void kernel_launch(void* const* d_in, const int* in_sizes, int n_in,
                              void* d_out, int out_size) {
    const float* x       = (const float*)d_in[0];
    const int*   eidx    = (const int*)  d_in[1];
    const float* W       = (const float*)d_in[2];
    const float* att_src = (const float*)d_in[3];
    const float* att_dst = (const float*)d_in[4];
    const float* bias    = (const float*)d_in[5];
    float*       out     = (float*)d_out;

    const int* src = eidx;
    const int* dst = eidx + EE;

    static SideStream ss;   // created once, host-side only (no device allocs)

    // fork: side stream builds the CSR while main stream runs prep+GEMM
    cudaEventRecord(ss.fork, 0);
    cudaStreamWaitEvent(ss.s, ss.fork, 0);

    // side chain (independent of prep/gemm):
    init_deg_kernel<<<(NN + 255) / 256, 256, 0, ss.s>>>();
    hist_kernel<<<(ET + 255) / 256, 256, 0, ss.s>>>(dst);
    scanA_kernel<<<NB, 512, 0, ss.s>>>();
    scanB_kernel<<<1, 64, 0, ss.s>>>();
    scanC_kernel<<<NB, 512, 0, ss.s>>>();
    fill_kernel<<<(ET + 255) / 256, 256, 0, ss.s>>>(src, dst);
    cudaEventRecord(ss.join, ss.s);

    // main chain:
    prep_kernel<<<(NN * INF_ + 255) / 256, 256>>>(x, W);
    {
        dim3 grid((NN + 127) / 128, HC / 128);   // (235, 4)
        gemm_mma_kernel<<<grid, 256>>>(att_src, att_dst);
    }

    // join, then aggregate needs both chains
    cudaStreamWaitEvent(0, ss.join, 0);
    aggregate_kernel<<<(NN + 7) / 8, 256>>>(out, bias);
}

// round 16
// speedup vs baseline: 1.2252x; 1.0109x over previous
#include <cuda_runtime.h>
#include <cuda_bf16.h>
#include <cuda_fp16.h>
#include <cstdint>

// Problem constants
#define NN   30000
#define EE   480000
#define ET   (EE + NN)
#define INF_ 256
#define OUTF 128
#define HH   4
#define HC   (HH * OUTF)      // 512
#define NEG_SLOPE 0.2f
#define NB   ((NN + 511) / 512)   // 59 scan blocks
#define WCAP 128                  // per-warp edge-weight smem cap

// ---------------- device scratch ----------------
__device__ __half         g_h[(size_t)NN * HC];        // projected features, fp16 (30.7 MB)
__device__ float          g_as[NN * HH];
__device__ float          g_ad[NN * HH];
__device__ __half         g_x[(size_t)NN * INF_];      // x in fp16 (15.4 MB)
__device__ __half         g_Wt[HC * INF_];             // W^T fp16 [512][256]
__device__ int            g_deg[NN];
__device__ int            g_off[NN + 1];
__device__ int            g_pos[NN];
__device__ int            g_bin[ET];
__device__ int            g_bsum[64];
__device__ int            g_bpre[64];

__device__ __forceinline__ float lrelu(float f) { return f > 0.0f ? f : NEG_SLOPE * f; }

__device__ __forceinline__ uint32_t smem_u32(const void* p) {
    uint32_t a;
    asm("{ .reg .u64 t; cvta.to.shared.u64 t, %1; cvt.u32.u64 %0, t; }" : "=r"(a) : "l"(p));
    return a;
}
__device__ __forceinline__ void ldsm4(uint32_t* r, uint32_t addr) {
    asm volatile("ldmatrix.sync.aligned.m8n8.x4.shared.b16 {%0,%1,%2,%3}, [%4];"
                 : "=r"(r[0]), "=r"(r[1]), "=r"(r[2]), "=r"(r[3]) : "r"(addr));
}
__device__ __forceinline__ void mma_f16(float* c, const uint32_t* a, const uint32_t* b) {
    asm volatile(
        "mma.sync.aligned.m16n8k16.row.col.f32.f16.f16.f32 "
        "{%0,%1,%2,%3}, {%4,%5,%6,%7}, {%8,%9}, {%0,%1,%2,%3};"
        : "+f"(c[0]), "+f"(c[1]), "+f"(c[2]), "+f"(c[3])
        : "r"(a[0]), "r"(a[1]), "r"(a[2]), "r"(a[3]), "r"(b[0]), "r"(b[1]));
}
__device__ __forceinline__ void cp16(uint32_t saddr, const void* gptr) {
    asm volatile("cp.async.ca.shared.global [%0], [%1], 16;"
                 :: "r"(saddr), "l"(gptr));
}
#define CP_COMMIT()  asm volatile("cp.async.commit_group;" ::: "memory")
#define CP_WAIT(n)   asm volatile("cp.async.wait_group %0;" :: "n"(n) : "memory")

// ---------------- 0) prep: x -> fp16; W^T fp16; zero attn accum ----
__global__ void prep_kernel(const float* __restrict__ x, const float* __restrict__ W) {
    const int idx = blockIdx.x * blockDim.x + threadIdx.x;
    if (idx < NN * INF_) {
        g_x[idx] = __float2half_rn(x[idx]);
    }
    if (idx < HC * INF_) {
        const int n = idx >> 8;
        const int k = idx & 255;
        g_Wt[idx] = __float2half_rn(W[(size_t)k * HC + n]);
    }
    if (idx < NN * HH) { g_as[idx] = 0.0f; g_ad[idx] = 0.0f; }
}

// head of the CSR side-chain: zero the degree histogram
__global__ void init_deg_kernel() {
    const int idx = blockIdx.x * blockDim.x + threadIdx.x;
    if (idx < NN) g_deg[idx] = 0;
}

__global__ void hist_kernel(const int* __restrict__ dst) {
    const int e = blockIdx.x * blockDim.x + threadIdx.x;
    if (e >= ET) return;
    const int d = (e < EE) ? dst[e] : (e - EE);
    atomicAdd(&g_deg[d], 1);
}

// ---------------- 1) GEMM via mma.sync fp16 (single term), cp.async 2-stage -------
// Block 128(M) x 128(N)=one head, 8 warps (4x2), warp tile 32x64.
__global__ void __launch_bounds__(256) gemm_mma_kernel(const float* __restrict__ att_src,
                                                       const float* __restrict__ att_dst) {
    __shared__ __align__(16) __half As[2][128][40];
    __shared__ __align__(16) __half Bs[2][128][40];

    const int tid    = threadIdx.x;
    const int lane   = tid & 31;
    const int wid    = tid >> 5;
    const int warp_m = wid & 3;
    const int warp_n = wid >> 2;
    const int bm     = blockIdx.x * 128;
    const int n0     = blockIdx.y * 128;
    const int head   = blockIdx.y;

    float acc[2][8][4];
#pragma unroll
    for (int i = 0; i < 2; i++)
#pragma unroll
        for (int j = 0; j < 8; j++)
#pragma unroll
            for (int k = 0; k < 4; k++) acc[i][j][k] = 0.0f;

    const uint32_t as_base = smem_u32(&As[0][0][0]);
    const uint32_t bs_base = smem_u32(&Bs[0][0][0]);
    const int a_row = warp_m * 32 + (lane & 15);
    const int a_col = (lane >> 4) * 8;
    const int b_row = warp_n * 64 + (lane & 7) + (lane >> 4) * 8;
    const int b_col = ((lane >> 3) & 1) * 8;

    const int NITER = 8;   // 8 K-chunks of 32

    auto prefetch = [&](int stage, int it) {
        const int k0 = it << 5;
#pragma unroll
        for (int i = 0; i < 2; i++) {
            const int idx = tid + i * 256;
            const int row = idx >> 2;
            const int seg = (idx & 3) * 8;
            const int gr  = bm + row;
            const int grc = (gr < NN) ? gr : 0;   // clamp; results discarded later
            cp16(as_base + (((stage * 128 + row) * 40) + seg) * 2,
                 g_x + (size_t)grc * INF_ + k0 + seg);
            cp16(bs_base + (((stage * 128 + row) * 40) + seg) * 2,
                 g_Wt + (size_t)(n0 + row) * INF_ + k0 + seg);
        }
        CP_COMMIT();
    };

    prefetch(0, 0);
#pragma unroll 1
    for (int it = 0; it < NITER; it++) {
        const int stage = it & 1;
        if (it + 1 < NITER) {
            prefetch(stage ^ 1, it + 1);
            CP_WAIT(1);
        } else {
            CP_WAIT(0);
        }
        __syncthreads();
#pragma unroll
        for (int ks = 0; ks < 2; ks++) {
            uint32_t af[2][4];
#pragma unroll
            for (int mt = 0; mt < 2; mt++) {
                const uint32_t addr = as_base +
                    ((stage * 128 + a_row + mt * 16) * 40 + ks * 16 + a_col) * 2;
                ldsm4(af[mt], addr);
            }
#pragma unroll
            for (int p = 0; p < 4; p++) {
                uint32_t bf[4];
                const uint32_t addr = bs_base +
                    ((stage * 128 + b_row + p * 16) * 40 + ks * 16 + b_col) * 2;
                ldsm4(bf, addr);
#pragma unroll
                for (int mt = 0; mt < 2; mt++) {
                    mma_f16(acc[mt][2 * p],     af[mt], bf);
                    mma_f16(acc[mt][2 * p + 1], af[mt], bf + 2);
                }
            }
        }
        __syncthreads();
    }

    // ---- epilogue: store g_h (fp16), fused attention dot partials ----
    const int r0 = lane >> 2;
    const int cq = (lane & 3) * 2;
    float da[2][2] = {{0.f, 0.f}, {0.f, 0.f}};
    float db[2][2] = {{0.f, 0.f}, {0.f, 0.f}};

#pragma unroll
    for (int mt = 0; mt < 2; mt++) {
        const int gm0 = bm + warp_m * 32 + mt * 16 + r0;
        const int gm1 = gm0 + 8;
#pragma unroll
        for (int nt = 0; nt < 8; nt++) {
            const int cih = warp_n * 64 + nt * 8 + cq;
            const int gc  = n0 + cih;
            const float s0 = att_src[head * OUTF + cih];
            const float s1 = att_src[head * OUTF + cih + 1];
            const float d0 = att_dst[head * OUTF + cih];
            const float d1 = att_dst[head * OUTF + cih + 1];
            const float c0 = acc[mt][nt][0], c1 = acc[mt][nt][1];
            const float c2 = acc[mt][nt][2], c3 = acc[mt][nt][3];
            da[mt][0] += c0 * s0 + c1 * s1;
            db[mt][0] += c0 * d0 + c1 * d1;
            da[mt][1] += c2 * s0 + c3 * s1;
            db[mt][1] += c2 * d0 + c3 * d1;
            if (gm0 < NN)
                *(__half2*)&g_h[(size_t)gm0 * HC + gc] = __floats2half2_rn(c0, c1);
            if (gm1 < NN)
                *(__half2*)&g_h[(size_t)gm1 * HC + gc] = __floats2half2_rn(c2, c3);
        }
    }
#pragma unroll
    for (int mt = 0; mt < 2; mt++)
#pragma unroll
        for (int h = 0; h < 2; h++) {
            da[mt][h] += __shfl_xor_sync(0xFFFFFFFFu, da[mt][h], 1);
            da[mt][h] += __shfl_xor_sync(0xFFFFFFFFu, da[mt][h], 2);
            db[mt][h] += __shfl_xor_sync(0xFFFFFFFFu, db[mt][h], 1);
            db[mt][h] += __shfl_xor_sync(0xFFFFFFFFu, db[mt][h], 2);
        }
    if ((lane & 3) == 0) {
#pragma unroll
        for (int mt = 0; mt < 2; mt++)
#pragma unroll
            for (int h = 0; h < 2; h++) {
                const int gm = bm + warp_m * 32 + mt * 16 + r0 + h * 8;
                if (gm < NN) {
                    atomicAdd(&g_as[gm * HH + head], da[mt][h]);
                    atomicAdd(&g_ad[gm * HH + head], db[mt][h]);
                }
            }
    }
}

// ---------------- 2) CSR build: hierarchical scan + fill ----------------
__global__ void __launch_bounds__(512) scanA_kernel() {
    __shared__ int sm[512];
    const int t = threadIdx.x;
    const int j = blockIdx.x * 512 + t;
    const int v = (j < NN) ? g_deg[j] : 0;
    sm[t] = v;
    __syncthreads();
#pragma unroll
    for (int s = 1; s < 512; s <<= 1) {
        const int u = (t >= s) ? sm[t - s] : 0;
        __syncthreads();
        sm[t] += u;
        __syncthreads();
    }
    if (j < NN) g_off[j] = sm[t] - v;
    if (t == 511) g_bsum[blockIdx.x] = sm[511];
}

__global__ void __launch_bounds__(64) scanB_kernel() {
    __shared__ int sm[64];
    const int t = threadIdx.x;
    const int v = (t < NB) ? g_bsum[t] : 0;
    sm[t] = v;
    __syncthreads();
#pragma unroll
    for (int s = 1; s < 64; s <<= 1) {
        const int u = (t >= s) ? sm[t - s] : 0;
        __syncthreads();
        sm[t] += u;
        __syncthreads();
    }
    if (t < NB) g_bpre[t] = sm[t] - v;
}

__global__ void __launch_bounds__(512) scanC_kernel() {
    const int j = blockIdx.x * 512 + threadIdx.x;
    if (j < NN) {
        const int o = g_off[j] + g_bpre[blockIdx.x];
        g_off[j] = o;
        g_pos[j] = o;
    }
    if (j == 0) g_off[NN] = ET;
}

__global__ void fill_kernel(const int* __restrict__ src, const int* __restrict__ dst) {
    const int e = blockIdx.x * blockDim.x + threadIdx.x;
    if (e >= ET) return;
    int s, d;
    if (e < EE) { s = src[e]; d = dst[e]; } else { s = d = e - EE; }
    const int p = atomicAdd(&g_pos[d], 1);
    g_bin[p] = s;
}

// ---------------- 3) gather aggregation: reg-carried alpha + smem src/weight cache ----
// One warp per dst node. Pass 1 computes alpha (kept in registers for the common
// deg<=32 case) and caches src ids in smem. Pass 2 reuses the register alpha for
// exp, caches exp in smem; normalized in place after the reduce. Pass 3 reads src
// from smem (LDS, short dependency chain) and the finished weight from smem.
__global__ void __launch_bounds__(256) aggregate_kernel(float* __restrict__ out,
                                                        const float* __restrict__ bias) {
    __shared__ __align__(16) float4 wbuf[8][WCAP];   // 16 KB
    __shared__ int sbuf[8][WCAP];                    // 4 KB
    const int wib  = threadIdx.x >> 5;               // warp in block
    const int gw   = (blockIdx.x * blockDim.x + threadIdx.x) >> 5;
    const int lane = threadIdx.x & 31;
    if (gw >= NN) return;
    const int d   = gw;
    const int off = g_off[d];
    const int end = g_off[d + 1];
    const float4 ad4 = *(const float4*)&g_ad[d * HH];

    // pass 1: per-head max; cache src ids; keep first-iteration alpha in registers
    float4 al0 = make_float4(0.f, 0.f, 0.f, 0.f);
    float4 m = make_float4(-1e30f, -1e30f, -1e30f, -1e30f);
    for (int i = off + lane; i < end; i += 32) {
        const int s = g_bin[i];
        const int idx = i - off;
        if (idx < WCAP) sbuf[wib][idx] = s;
        const float4 as4 = *(const float4*)&g_as[s * HH];
        float4 al;
        al.x = lrelu(as4.x + ad4.x);
        al.y = lrelu(as4.y + ad4.y);
        al.z = lrelu(as4.z + ad4.z);
        al.w = lrelu(as4.w + ad4.w);
        if (i == off + lane) al0 = al;   // register-carry for pass 2
        m.x = fmaxf(m.x, al.x);
        m.y = fmaxf(m.y, al.y);
        m.z = fmaxf(m.z, al.z);
        m.w = fmaxf(m.w, al.w);
    }
#pragma unroll
    for (int o = 16; o; o >>= 1) {
        m.x = fmaxf(m.x, __shfl_xor_sync(0xFFFFFFFFu, m.x, o));
        m.y = fmaxf(m.y, __shfl_xor_sync(0xFFFFFFFFu, m.y, o));
        m.z = fmaxf(m.z, __shfl_xor_sync(0xFFFFFFFFu, m.z, o));
        m.w = fmaxf(m.w, __shfl_xor_sync(0xFFFFFFFFu, m.w, o));
    }
    // pass 2: denominators; reuse register alpha on first iteration; cache exp in smem
    float4 den = make_float4(0.f, 0.f, 0.f, 0.f);
    for (int i = off + lane; i < end; i += 32) {
        float4 al;
        if (i == off + lane) {
            al = al0;
        } else {   // deg > 32 only (~3% of nodes): recompute
            const float4 as4 = *(const float4*)&g_as[g_bin[i] * HH];
            al.x = lrelu(as4.x + ad4.x);
            al.y = lrelu(as4.y + ad4.y);
            al.z = lrelu(as4.z + ad4.z);
            al.w = lrelu(as4.w + ad4.w);
        }
        float4 ex;
        ex.x = __expf(al.x - m.x);
        ex.y = __expf(al.y - m.y);
        ex.z = __expf(al.z - m.z);
        ex.w = __expf(al.w - m.w);
        den.x += ex.x; den.y += ex.y; den.z += ex.z; den.w += ex.w;
        const int idx = i - off;
        if (idx < WCAP) wbuf[wib][idx] = ex;
    }
#pragma unroll
    for (int o = 16; o; o >>= 1) {
        den.x += __shfl_xor_sync(0xFFFFFFFFu, den.x, o);
        den.y += __shfl_xor_sync(0xFFFFFFFFu, den.y, o);
        den.z += __shfl_xor_sync(0xFFFFFFFFu, den.z, o);
        den.w += __shfl_xor_sync(0xFFFFFFFFu, den.w, o);
    }
    const float4 inv = make_float4(0.25f / den.x, 0.25f / den.y, 0.25f / den.z, 0.25f / den.w);
    __syncwarp();
    // normalize cached weights in place
    {
        const int cnt = end - off;
        const int lim = cnt < WCAP ? cnt : WCAP;
        for (int idx = lane; idx < lim; idx += 32) {
            float4 w4 = wbuf[wib][idx];
            w4.x *= inv.x; w4.y *= inv.y; w4.z *= inv.z; w4.w *= inv.w;
            wbuf[wib][idx] = w4;
        }
    }
    __syncwarp();

    // pass 3: weighted feature gather (fp16 features; lane owns 4 channels per head)
    float4 acc = make_float4(0.f, 0.f, 0.f, 0.f);
    const int cb = lane * 4;

    auto body = [&](int i) {
        const int idx = i - off;
        float4 w4;
        int s;
        if (idx < WCAP) {
            w4 = wbuf[wib][idx];
            s  = sbuf[wib][idx];
        } else {   // astronomically rare (deg > 128): recompute inline
            s = g_bin[i];
            const float4 as4 = *(const float4*)&g_as[s * HH];
            w4.x = __expf(lrelu(as4.x + ad4.x) - m.x) * inv.x;
            w4.y = __expf(lrelu(as4.y + ad4.y) - m.y) * inv.y;
            w4.z = __expf(lrelu(as4.z + ad4.z) - m.z) * inv.z;
            w4.w = __expf(lrelu(as4.w + ad4.w) - m.w) * inv.w;
        }
        const __half* hs = &g_h[(size_t)s * HC];
        const uint2 u0 = *(const uint2*)(hs + 0 * OUTF + cb);
        const uint2 u1 = *(const uint2*)(hs + 1 * OUTF + cb);
        const uint2 u2 = *(const uint2*)(hs + 2 * OUTF + cb);
        const uint2 u3 = *(const uint2*)(hs + 3 * OUTF + cb);
        const float2 a0 = __half22float2(*(const __half2*)&u0.x);
        const float2 b0 = __half22float2(*(const __half2*)&u0.y);
        const float2 a1 = __half22float2(*(const __half2*)&u1.x);
        const float2 b1 = __half22float2(*(const __half2*)&u1.y);
        const float2 a2 = __half22float2(*(const __half2*)&u2.x);
        const float2 b2 = __half22float2(*(const __half2*)&u2.y);
        const float2 a3 = __half22float2(*(const __half2*)&u3.x);
        const float2 b3 = __half22float2(*(const __half2*)&u3.y);
        acc.x += w4.x * a0.x + w4.y * a1.x + w4.z * a2.x + w4.w * a3.x;
        acc.y += w4.x * a0.y + w4.y * a1.y + w4.z * a2.y + w4.w * a3.y;
        acc.z += w4.x * b0.x + w4.y * b1.x + w4.z * b2.x + w4.w * b3.x;
        acc.w += w4.x * b0.y + w4.y * b1.y + w4.z * b2.y + w4.w * b3.y;
    };
    int i = off;
    for (; i + 1 < end; i += 2) { body(i); body(i + 1); }
    if (i < end) body(i);

    const float4 b4 = *(const float4*)&bias[cb];
    float4 r;
    r.x = tanhf(acc.x + b4.x);
    r.y = tanhf(acc.y + b4.y);
    r.z = tanhf(acc.z + b4.z);
    r.w = tanhf(acc.w + b4.w);
    *(float4*)&out[(size_t)d * OUTF + cb] = r;
}

// ---------------- launch: two-stream fork/join (graph-capturable) ----------------
struct SideStream {
    cudaStream_t s;
    cudaEvent_t  fork, join;
    SideStream() {
        cudaStreamCreateWithFlags(&s, cudaStreamNonBlocking);
        cudaEventCreateWithFlags(&fork, cudaEventDisableTiming);
        cudaEventCreateWithFlags(&join, cudaEventDisableTiming);
    }
};

extern "C" void kernel_launch(void* const* d_in, const int* in_sizes, int n_in,
                              void* d_out, int out_size) {
    const float* x       = (const float*)d_in[0];
    const int*   eidx    = (const int*)  d_in[1];
    const float* W       = (const float*)d_in[2];
    const float* att_src = (const float*)d_in[3];
    const float* att_dst = (const float*)d_in[4];
    const float* bias    = (const float*)d_in[5];
    float*       out     = (float*)d_out;

    const int* src = eidx;
    const int* dst = eidx + EE;

    static SideStream ss;   // created once, host-side only (no device allocs)

    // fork: side stream builds the CSR while main stream runs prep+GEMM
    cudaEventRecord(ss.fork, 0);
    cudaStreamWaitEvent(ss.s, ss.fork, 0);

    // side chain (independent of prep/gemm):
    init_deg_kernel<<<(NN + 255) / 256, 256, 0, ss.s>>>();
    hist_kernel<<<(ET + 255) / 256, 256, 0, ss.s>>>(dst);
    scanA_kernel<<<NB, 512, 0, ss.s>>>();
    scanB_kernel<<<1, 64, 0, ss.s>>>();
    scanC_kernel<<<NB, 512, 0, ss.s>>>();
    fill_kernel<<<(ET + 255) / 256, 256, 0, ss.s>>>(src, dst);
    cudaEventRecord(ss.join, ss.s);

    // main chain:
    prep_kernel<<<(NN * INF_ + 255) / 256, 256>>>(x, W);
    {
        dim3 grid((NN + 127) / 128, HC / 128);   // (235, 4)
        gemm_mma_kernel<<<grid, 256>>>(att_src, att_dst);
    }

    // join, then aggregate needs both chains
    cudaStreamWaitEvent(0, ss.join, 0);
    aggregate_kernel<<<(NN + 7) / 8, 256>>>(out, bias);
}

// round 17
// speedup vs baseline: 1.3599x; 1.1099x over previous
#include <cuda_runtime.h>
#include <cuda_bf16.h>
#include <cuda_fp16.h>
#include <cstdint>

// Problem constants
#define NN   30000
#define EE   480000
#define ET   (EE + NN)
#define INF_ 256
#define OUTF 128
#define HH   4
#define HC   (HH * OUTF)      // 512
#define NEG_SLOPE 0.2f
#define NB   ((NN + 511) / 512)   // 59 scan blocks
#define WCAP 128                  // per-warp edge-weight smem cap

// ---------------- device scratch ----------------
__device__ __half         g_h[(size_t)NN * HC];        // projected features, fp16 (30.7 MB)
__device__ float          g_as[NN * HH];
__device__ float          g_ad[NN * HH];
__device__ __half         g_x[(size_t)NN * INF_];      // x in fp16 (15.4 MB)
__device__ __half         g_Wt[HC * INF_];             // W^T fp16 [512][256]
__device__ int            g_deg[NN];
__device__ int            g_off[NN + 1];
__device__ int            g_pos[NN];
__device__ int            g_bin[ET];
__device__ int            g_bsum[64];
__device__ int            g_bpre[64];

__device__ __forceinline__ float lrelu(float f) { return f > 0.0f ? f : NEG_SLOPE * f; }

__device__ __forceinline__ uint32_t smem_u32(const void* p) {
    uint32_t a;
    asm("{ .reg .u64 t; cvta.to.shared.u64 t, %1; cvt.u32.u64 %0, t; }" : "=r"(a) : "l"(p));
    return a;
}
__device__ __forceinline__ void ldsm4(uint32_t* r, uint32_t addr) {
    asm volatile("ldmatrix.sync.aligned.m8n8.x4.shared.b16 {%0,%1,%2,%3}, [%4];"
                 : "=r"(r[0]), "=r"(r[1]), "=r"(r[2]), "=r"(r[3]) : "r"(addr));
}
__device__ __forceinline__ void mma_f16(float* c, const uint32_t* a, const uint32_t* b) {
    asm volatile(
        "mma.sync.aligned.m16n8k16.row.col.f32.f16.f16.f32 "
        "{%0,%1,%2,%3}, {%4,%5,%6,%7}, {%8,%9}, {%0,%1,%2,%3};"
        : "+f"(c[0]), "+f"(c[1]), "+f"(c[2]), "+f"(c[3])
        : "r"(a[0]), "r"(a[1]), "r"(a[2]), "r"(a[3]), "r"(b[0]), "r"(b[1]));
}
__device__ __forceinline__ void cp16(uint32_t saddr, const void* gptr) {
    asm volatile("cp.async.ca.shared.global [%0], [%1], 16;"
                 :: "r"(saddr), "l"(gptr));
}
#define CP_COMMIT()  asm volatile("cp.async.commit_group;" ::: "memory")
#define CP_WAIT(n)   asm volatile("cp.async.wait_group %0;" :: "n"(n) : "memory")

// ---------------- 0a) prep_x (main stream): x -> fp16, vectorized 8/thread ----
__global__ void prep_x_kernel(const float* __restrict__ x) {
    const int t = blockIdx.x * blockDim.x + threadIdx.x;
    const int base = t * 8;
    if (base >= NN * INF_) return;
    const float4 v0 = *(const float4*)&x[base];
    const float4 v1 = *(const float4*)&x[base + 4];
    __half2 h[4];
    h[0] = __floats2half2_rn(v0.x, v0.y);
    h[1] = __floats2half2_rn(v0.z, v0.w);
    h[2] = __floats2half2_rn(v1.x, v1.y);
    h[3] = __floats2half2_rn(v1.z, v1.w);
    *(uint4*)&g_x[base] = *(uint4*)h;
}

// ---------------- 0b) prep_w (side stream): W^T fp16 + zero attn accum + deg ----
__global__ void prep_w_kernel(const float* __restrict__ W) {
    const int idx = blockIdx.x * blockDim.x + threadIdx.x;
    if (idx < HC * INF_) {
        const int n = idx >> 8;
        const int k = idx & 255;
        g_Wt[idx] = __float2half_rn(W[(size_t)k * HC + n]);
    }
    if (idx < NN * HH) { g_as[idx] = 0.0f; g_ad[idx] = 0.0f; }
    if (idx < NN) g_deg[idx] = 0;
}

__global__ void hist_kernel(const int* __restrict__ dst) {
    const int e = blockIdx.x * blockDim.x + threadIdx.x;
    if (e >= ET) return;
    const int d = (e < EE) ? dst[e] : (e - EE);
    atomicAdd(&g_deg[d], 1);
}

// ---------------- 1) GEMM via mma.sync fp16 (single term), cp.async 2-stage -------
// Block 128(M) x 128(N)=one head, 8 warps (4x2), warp tile 32x64.
__global__ void __launch_bounds__(256) gemm_mma_kernel(const float* __restrict__ att_src,
                                                       const float* __restrict__ att_dst) {
    __shared__ __align__(16) __half As[2][128][40];
    __shared__ __align__(16) __half Bs[2][128][40];

    const int tid    = threadIdx.x;
    const int lane   = tid & 31;
    const int wid    = tid >> 5;
    const int warp_m = wid & 3;
    const int warp_n = wid >> 2;
    const int bm     = blockIdx.x * 128;
    const int n0     = blockIdx.y * 128;
    const int head   = blockIdx.y;

    float acc[2][8][4];
#pragma unroll
    for (int i = 0; i < 2; i++)
#pragma unroll
        for (int j = 0; j < 8; j++)
#pragma unroll
            for (int k = 0; k < 4; k++) acc[i][j][k] = 0.0f;

    const uint32_t as_base = smem_u32(&As[0][0][0]);
    const uint32_t bs_base = smem_u32(&Bs[0][0][0]);
    const int a_row = warp_m * 32 + (lane & 15);
    const int a_col = (lane >> 4) * 8;
    const int b_row = warp_n * 64 + (lane & 7) + (lane >> 4) * 8;
    const int b_col = ((lane >> 3) & 1) * 8;

    const int NITER = 8;   // 8 K-chunks of 32

    auto prefetch = [&](int stage, int it) {
        const int k0 = it << 5;
#pragma unroll
        for (int i = 0; i < 2; i++) {
            const int idx = tid + i * 256;
            const int row = idx >> 2;
            const int seg = (idx & 3) * 8;
            const int gr  = bm + row;
            const int grc = (gr < NN) ? gr : 0;   // clamp; results discarded later
            cp16(as_base + (((stage * 128 + row) * 40) + seg) * 2,
                 g_x + (size_t)grc * INF_ + k0 + seg);
            cp16(bs_base + (((stage * 128 + row) * 40) + seg) * 2,
                 g_Wt + (size_t)(n0 + row) * INF_ + k0 + seg);
        }
        CP_COMMIT();
    };

    prefetch(0, 0);
#pragma unroll 1
    for (int it = 0; it < NITER; it++) {
        const int stage = it & 1;
        if (it + 1 < NITER) {
            prefetch(stage ^ 1, it + 1);
            CP_WAIT(1);
        } else {
            CP_WAIT(0);
        }
        __syncthreads();
#pragma unroll
        for (int ks = 0; ks < 2; ks++) {
            uint32_t af[2][4];
#pragma unroll
            for (int mt = 0; mt < 2; mt++) {
                const uint32_t addr = as_base +
                    ((stage * 128 + a_row + mt * 16) * 40 + ks * 16 + a_col) * 2;
                ldsm4(af[mt], addr);
            }
#pragma unroll
            for (int p = 0; p < 4; p++) {
                uint32_t bf[4];
                const uint32_t addr = bs_base +
                    ((stage * 128 + b_row + p * 16) * 40 + ks * 16 + b_col) * 2;
                ldsm4(bf, addr);
#pragma unroll
                for (int mt = 0; mt < 2; mt++) {
                    mma_f16(acc[mt][2 * p],     af[mt], bf);
                    mma_f16(acc[mt][2 * p + 1], af[mt], bf + 2);
                }
            }
        }
        __syncthreads();
    }

    // ---- epilogue: store g_h (fp16), fused attention dot partials ----
    const int r0 = lane >> 2;
    const int cq = (lane & 3) * 2;
    float da[2][2] = {{0.f, 0.f}, {0.f, 0.f}};
    float db[2][2] = {{0.f, 0.f}, {0.f, 0.f}};

#pragma unroll
    for (int mt = 0; mt < 2; mt++) {
        const int gm0 = bm + warp_m * 32 + mt * 16 + r0;
        const int gm1 = gm0 + 8;
#pragma unroll
        for (int nt = 0; nt < 8; nt++) {
            const int cih = warp_n * 64 + nt * 8 + cq;
            const int gc  = n0 + cih;
            const float s0 = att_src[head * OUTF + cih];
            const float s1 = att_src[head * OUTF + cih + 1];
            const float d0 = att_dst[head * OUTF + cih];
            const float d1 = att_dst[head * OUTF + cih + 1];
            const float c0 = acc[mt][nt][0], c1 = acc[mt][nt][1];
            const float c2 = acc[mt][nt][2], c3 = acc[mt][nt][3];
            da[mt][0] += c0 * s0 + c1 * s1;
            db[mt][0] += c0 * d0 + c1 * d1;
            da[mt][1] += c2 * s0 + c3 * s1;
            db[mt][1] += c2 * d0 + c3 * d1;
            if (gm0 < NN)
                *(__half2*)&g_h[(size_t)gm0 * HC + gc] = __floats2half2_rn(c0, c1);
            if (gm1 < NN)
                *(__half2*)&g_h[(size_t)gm1 * HC + gc] = __floats2half2_rn(c2, c3);
        }
    }
#pragma unroll
    for (int mt = 0; mt < 2; mt++)
#pragma unroll
        for (int h = 0; h < 2; h++) {
            da[mt][h] += __shfl_xor_sync(0xFFFFFFFFu, da[mt][h], 1);
            da[mt][h] += __shfl_xor_sync(0xFFFFFFFFu, da[mt][h], 2);
            db[mt][h] += __shfl_xor_sync(0xFFFFFFFFu, db[mt][h], 1);
            db[mt][h] += __shfl_xor_sync(0xFFFFFFFFu, db[mt][h], 2);
        }
    if ((lane & 3) == 0) {
#pragma unroll
        for (int mt = 0; mt < 2; mt++)
#pragma unroll
            for (int h = 0; h < 2; h++) {
                const int gm = bm + warp_m * 32 + mt * 16 + r0 + h * 8;
                if (gm < NN) {
                    atomicAdd(&g_as[gm * HH + head], da[mt][h]);
                    atomicAdd(&g_ad[gm * HH + head], db[mt][h]);
                }
            }
    }
}

// ---------------- 2) CSR build: hierarchical scan + fill ----------------
__global__ void __launch_bounds__(512) scanA_kernel() {
    __shared__ int sm[512];
    const int t = threadIdx.x;
    const int j = blockIdx.x * 512 + t;
    const int v = (j < NN) ? g_deg[j] : 0;
    sm[t] = v;
    __syncthreads();
#pragma unroll
    for (int s = 1; s < 512; s <<= 1) {
        const int u = (t >= s) ? sm[t - s] : 0;
        __syncthreads();
        sm[t] += u;
        __syncthreads();
    }
    if (j < NN) g_off[j] = sm[t] - v;
    if (t == 511) g_bsum[blockIdx.x] = sm[511];
}

__global__ void __launch_bounds__(64) scanB_kernel() {
    __shared__ int sm[64];
    const int t = threadIdx.x;
    const int v = (t < NB) ? g_bsum[t] : 0;
    sm[t] = v;
    __syncthreads();
#pragma unroll
    for (int s = 1; s < 64; s <<= 1) {
        const int u = (t >= s) ? sm[t - s] : 0;
        __syncthreads();
        sm[t] += u;
        __syncthreads();
    }
    if (t < NB) g_bpre[t] = sm[t] - v;
}

__global__ void __launch_bounds__(512) scanC_kernel() {
    const int j = blockIdx.x * 512 + threadIdx.x;
    if (j < NN) {
        const int o = g_off[j] + g_bpre[blockIdx.x];
        g_off[j] = o;
        g_pos[j] = o;
    }
    if (j == 0) g_off[NN] = ET;
}

__global__ void fill_kernel(const int* __restrict__ src, const int* __restrict__ dst) {
    const int e = blockIdx.x * blockDim.x + threadIdx.x;
    if (e >= ET) return;
    int s, d;
    if (e < EE) { s = src[e]; d = dst[e]; } else { s = d = e - EE; }
    const int p = atomicAdd(&g_pos[d], 1);
    g_bin[p] = s;
}

// ---------------- 3) gather aggregation: reg-carried alpha + smem src/weight cache ----
__global__ void __launch_bounds__(256) aggregate_kernel(float* __restrict__ out,
                                                        const float* __restrict__ bias) {
    __shared__ __align__(16) float4 wbuf[8][WCAP];   // 16 KB
    __shared__ int sbuf[8][WCAP];                    // 4 KB
    const int wib  = threadIdx.x >> 5;               // warp in block
    const int gw   = (blockIdx.x * blockDim.x + threadIdx.x) >> 5;
    const int lane = threadIdx.x & 31;
    if (gw >= NN) return;
    const int d   = gw;
    const int off = g_off[d];
    const int end = g_off[d + 1];
    const float4 ad4 = *(const float4*)&g_ad[d * HH];

    // pass 1: per-head max; cache src ids; keep first-iteration alpha in registers
    float4 al0 = make_float4(0.f, 0.f, 0.f, 0.f);
    float4 m = make_float4(-1e30f, -1e30f, -1e30f, -1e30f);
    for (int i = off + lane; i < end; i += 32) {
        const int s = g_bin[i];
        const int idx = i - off;
        if (idx < WCAP) sbuf[wib][idx] = s;
        const float4 as4 = *(const float4*)&g_as[s * HH];
        float4 al;
        al.x = lrelu(as4.x + ad4.x);
        al.y = lrelu(as4.y + ad4.y);
        al.z = lrelu(as4.z + ad4.z);
        al.w = lrelu(as4.w + ad4.w);
        if (i == off + lane) al0 = al;   // register-carry for pass 2
        m.x = fmaxf(m.x, al.x);
        m.y = fmaxf(m.y, al.y);
        m.z = fmaxf(m.z, al.z);
        m.w = fmaxf(m.w, al.w);
    }
#pragma unroll
    for (int o = 16; o; o >>= 1) {
        m.x = fmaxf(m.x, __shfl_xor_sync(0xFFFFFFFFu, m.x, o));
        m.y = fmaxf(m.y, __shfl_xor_sync(0xFFFFFFFFu, m.y, o));
        m.z = fmaxf(m.z, __shfl_xor_sync(0xFFFFFFFFu, m.z, o));
        m.w = fmaxf(m.w, __shfl_xor_sync(0xFFFFFFFFu, m.w, o));
    }
    // pass 2: denominators; reuse register alpha on first iteration; cache exp in smem
    float4 den = make_float4(0.f, 0.f, 0.f, 0.f);
    for (int i = off + lane; i < end; i += 32) {
        float4 al;
        if (i == off + lane) {
            al = al0;
        } else {   // deg > 32 only (~3% of nodes): recompute
            const float4 as4 = *(const float4*)&g_as[g_bin[i] * HH];
            al.x = lrelu(as4.x + ad4.x);
            al.y = lrelu(as4.y + ad4.y);
            al.z = lrelu(as4.z + ad4.z);
            al.w = lrelu(as4.w + ad4.w);
        }
        float4 ex;
        ex.x = __expf(al.x - m.x);
        ex.y = __expf(al.y - m.y);
        ex.z = __expf(al.z - m.z);
        ex.w = __expf(al.w - m.w);
        den.x += ex.x; den.y += ex.y; den.z += ex.z; den.w += ex.w;
        const int idx = i - off;
        if (idx < WCAP) wbuf[wib][idx] = ex;
    }
#pragma unroll
    for (int o = 16; o; o >>= 1) {
        den.x += __shfl_xor_sync(0xFFFFFFFFu, den.x, o);
        den.y += __shfl_xor_sync(0xFFFFFFFFu, den.y, o);
        den.z += __shfl_xor_sync(0xFFFFFFFFu, den.z, o);
        den.w += __shfl_xor_sync(0xFFFFFFFFu, den.w, o);
    }
    const float4 inv = make_float4(0.25f / den.x, 0.25f / den.y, 0.25f / den.z, 0.25f / den.w);
    __syncwarp();
    // normalize cached weights in place
    {
        const int cnt = end - off;
        const int lim = cnt < WCAP ? cnt : WCAP;
        for (int idx = lane; idx < lim; idx += 32) {
            float4 w4 = wbuf[wib][idx];
            w4.x *= inv.x; w4.y *= inv.y; w4.z *= inv.z; w4.w *= inv.w;
            wbuf[wib][idx] = w4;
        }
    }
    __syncwarp();

    // pass 3: weighted feature gather (fp16 features; lane owns 4 channels per head)
    float4 acc = make_float4(0.f, 0.f, 0.f, 0.f);
    const int cb = lane * 4;

    auto body = [&](int i) {
        const int idx = i - off;
        float4 w4;
        int s;
        if (idx < WCAP) {
            w4 = wbuf[wib][idx];
            s  = sbuf[wib][idx];
        } else {   // astronomically rare (deg > 128): recompute inline
            s = g_bin[i];
            const float4 as4 = *(const float4*)&g_as[s * HH];
            w4.x = __expf(lrelu(as4.x + ad4.x) - m.x) * inv.x;
            w4.y = __expf(lrelu(as4.y + ad4.y) - m.y) * inv.y;
            w4.z = __expf(lrelu(as4.z + ad4.z) - m.z) * inv.z;
            w4.w = __expf(lrelu(as4.w + ad4.w) - m.w) * inv.w;
        }
        const __half* hs = &g_h[(size_t)s * HC];
        const uint2 u0 = *(const uint2*)(hs + 0 * OUTF + cb);
        const uint2 u1 = *(const uint2*)(hs + 1 * OUTF + cb);
        const uint2 u2 = *(const uint2*)(hs + 2 * OUTF + cb);
        const uint2 u3 = *(const uint2*)(hs + 3 * OUTF + cb);
        const float2 a0 = __half22float2(*(const __half2*)&u0.x);
        const float2 b0 = __half22float2(*(const __half2*)&u0.y);
        const float2 a1 = __half22float2(*(const __half2*)&u1.x);
        const float2 b1 = __half22float2(*(const __half2*)&u1.y);
        const float2 a2 = __half22float2(*(const __half2*)&u2.x);
        const float2 b2 = __half22float2(*(const __half2*)&u2.y);
        const float2 a3 = __half22float2(*(const __half2*)&u3.x);
        const float2 b3 = __half22float2(*(const __half2*)&u3.y);
        acc.x += w4.x * a0.x + w4.y * a1.x + w4.z * a2.x + w4.w * a3.x;
        acc.y += w4.x * a0.y + w4.y * a1.y + w4.z * a2.y + w4.w * a3.y;
        acc.z += w4.x * b0.x + w4.y * b1.x + w4.z * b2.x + w4.w * b3.x;
        acc.w += w4.x * b0.y + w4.y * b1.y + w4.z * b2.y + w4.w * b3.y;
    };
    int i = off;
    for (; i + 1 < end; i += 2) { body(i); body(i + 1); }
    if (i < end) body(i);

    const float4 b4 = *(const float4*)&bias[cb];
    float4 r;
    r.x = tanhf(acc.x + b4.x);
    r.y = tanhf(acc.y + b4.y);
    r.z = tanhf(acc.z + b4.z);
    r.w = tanhf(acc.w + b4.w);
    *(float4*)&out[(size_t)d * OUTF + cb] = r;
}

// ---------------- launch: two-stream fork/join (graph-capturable) ----------------
struct SideStream {
    cudaStream_t s;
    cudaEvent_t  fork, wready, join;
    SideStream() {
        cudaStreamCreateWithFlags(&s, cudaStreamNonBlocking);
        cudaEventCreateWithFlags(&fork,   cudaEventDisableTiming);
        cudaEventCreateWithFlags(&wready, cudaEventDisableTiming);
        cudaEventCreateWithFlags(&join,   cudaEventDisableTiming);
    }
};

extern "C" void kernel_launch(void* const* d_in, const int* in_sizes, int n_in,
                              void* d_out, int out_size) {
    const float* x       = (const float*)d_in[0];
    const int*   eidx    = (const int*)  d_in[1];
    const float* W       = (const float*)d_in[2];
    const float* att_src = (const float*)d_in[3];
    const float* att_dst = (const float*)d_in[4];
    const float* bias    = (const float*)d_in[5];
    float*       out     = (float*)d_out;

    const int* src = eidx;
    const int* dst = eidx + EE;

    static SideStream ss;   // created once, host-side only (no device allocs)

    // fork
    cudaEventRecord(ss.fork, 0);
    cudaStreamWaitEvent(ss.s, ss.fork, 0);

    // side chain: W prep (gemm dependency, tiny) first, then CSR build
    prep_w_kernel<<<(HC * INF_ + 255) / 256, 256, 0, ss.s>>>(W);
    cudaEventRecord(ss.wready, ss.s);
    hist_kernel<<<(ET + 255) / 256, 256, 0, ss.s>>>(dst);
    scanA_kernel<<<NB, 512, 0, ss.s>>>();
    scanB_kernel<<<1, 64, 0, ss.s>>>();
    scanC_kernel<<<NB, 512, 0, ss.s>>>();
    fill_kernel<<<(ET + 255) / 256, 256, 0, ss.s>>>(src, dst);
    cudaEventRecord(ss.join, ss.s);

    // main chain: x conversion runs concurrently with prep_w
    prep_x_kernel<<<(NN * INF_ / 8 + 255) / 256, 256>>>(x);
    cudaStreamWaitEvent(0, ss.wready, 0);   // gemm needs g_Wt + zeroed g_as/g_ad
    {
        dim3 grid((NN + 127) / 128, HC / 128);   // (235, 4)
        gemm_mma_kernel<<<grid, 256>>>(att_src, att_dst);
    }

    // join, then aggregate needs both chains
    cudaStreamWaitEvent(0, ss.join, 0);
    aggregate_kernel<<<(NN + 7) / 8, 256>>>(out, bias);
}